// round 11
// baseline (speedup 1.0000x reference)
#include <cuda_runtime.h>
#include <math.h>

#define T 256
#define H 1024
#define E 256
#define I_DIM 256
#define SEG_CAP 8
#define NSEG_MAX 544

typedef unsigned long long u64;

// ---- static scratch ----
__device__ int   d_cnt[E];
__device__ int   d_tokbuf[E * T];
__device__ float d_wbuf[E * T];
__device__ int   d_nseg;
__device__ int   d_seg_e[NSEG_MAX];
__device__ int   d_seg_nt[NSEG_MAX];
__device__ int   d_seg_tok[NSEG_MAX * SEG_CAP];
__device__ float d_seg_wt[NSEG_MAX * SEG_CAP];
// ps: per-seg [256 i][4 token-pair u64]  (f32x2 = {tok2p, tok2p+1})
__device__ __align__(16) u64 d_ps[NSEG_MAX * I_DIM * 4];

// ---- f32x2 helpers ----
__device__ __forceinline__ u64 dup2f(float v) {
    u64 r; asm("mov.b64 %0,{%1,%1};" : "=l"(r) : "f"(v)); return r;
}
__device__ __forceinline__ u64 pk2(float a, float b) {
    u64 r; asm("mov.b64 %0,{%1,%2};" : "=l"(r) : "f"(a), "f"(b)); return r;
}
__device__ __forceinline__ u64 fma2(u64 a, u64 b, u64 c) {
    u64 d; asm("fma.rn.f32x2 %0,%1,%2,%3;" : "=l"(d) : "l"(a), "l"(b), "l"(c)); return d;
}
__device__ __forceinline__ u64 add2(u64 a, u64 b) {
    u64 d; asm("add.rn.f32x2 %0,%1,%2;" : "=l"(d) : "l"(a), "l"(b)); return d;
}
__device__ __forceinline__ float2 unpk(u64 a) {
    float2 f; asm("mov.b64 {%0,%1},%2;" : "=f"(f.x), "=f"(f.y) : "l"(a)); return f;
}

// ============================================================
// 0) init: zero output + per-expert counters
// ============================================================
__global__ void k_init(float4* y)
{
    y[blockIdx.x * 256 + threadIdx.x] = make_float4(0.f, 0.f, 0.f, 0.f);
    if (blockIdx.x == 0) d_cnt[threadIdx.x] = 0;
}

// ============================================================
// 1) gate logits + noaux_tc routing. 4 tokens per block.
// ============================================================
__global__ void k_route(const float* __restrict__ x,
                        const float* __restrict__ gw,
                        const float* __restrict__ ebias)
{
    __shared__ float xs[4][H];
    __shared__ float s_scores[4][E];
    __shared__ float s_sc[4][E];

    int tid  = threadIdx.x;
    int lane = tid & 31;
    int wid  = tid >> 5;
    int t0   = blockIdx.x * 4;

    for (int t = 0; t < 4; t++)
        for (int k = tid; k < H; k += 256)
            xs[t][k] = x[(t0 + t) * H + k];
    __syncthreads();

    for (int eo = 0; eo < 32; eo++) {
        int e = wid * 32 + eo;
        const float* wr = gw + e * H;
        float a0 = 0.f, a1 = 0.f, a2 = 0.f, a3 = 0.f;
        #pragma unroll 4
        for (int k = 0; k < 32; k++) {
            float wv = wr[k * 32 + lane];
            a0 += wv * xs[0][k * 32 + lane];
            a1 += wv * xs[1][k * 32 + lane];
            a2 += wv * xs[2][k * 32 + lane];
            a3 += wv * xs[3][k * 32 + lane];
        }
        for (int off = 16; off; off >>= 1) {
            a0 += __shfl_xor_sync(~0u, a0, off);
            a1 += __shfl_xor_sync(~0u, a1, off);
            a2 += __shfl_xor_sync(~0u, a2, off);
            a3 += __shfl_xor_sync(~0u, a3, off);
        }
        if (lane == 0) {
            float b = ebias[e];
            float s;
            s = 1.f / (1.f + expf(-a0)); s_scores[0][e] = s; s_sc[0][e] = s + b;
            s = 1.f / (1.f + expf(-a1)); s_scores[1][e] = s; s_sc[1][e] = s + b;
            s = 1.f / (1.f + expf(-a2)); s_scores[2][e] = s; s_sc[2][e] = s + b;
            s = 1.f / (1.f + expf(-a3)); s_scores[3][e] = s; s_sc[3][e] = s + b;
        }
    }
    __syncthreads();

    if (wid < 4) {
        int t     = wid;
        int tglob = t0 + t;

        float gs[8];
        #pragma unroll
        for (int g = 0; g < 8; g++) {
            float v  = s_sc[t][g * 32 + lane];
            float m1 = v; int i1 = lane;
            for (int off = 16; off; off >>= 1) {
                float ov = __shfl_xor_sync(~0u, m1, off);
                int   oi = __shfl_xor_sync(~0u, i1, off);
                if (ov > m1 || (ov == m1 && oi < i1)) { m1 = ov; i1 = oi; }
            }
            float v2 = (lane == i1) ? -INFINITY : v;
            for (int off = 16; off; off >>= 1)
                v2 = fmaxf(v2, __shfl_xor_sync(~0u, v2, off));
            gs[g] = m1 + v2;
        }

        unsigned gmask = 0;
        #pragma unroll
        for (int r = 0; r < 4; r++) {
            float bv = -INFINITY; int bg = 0;
            #pragma unroll
            for (int g = 0; g < 8; g++)
                if (!((gmask >> g) & 1) && gs[g] > bv) { bv = gs[g]; bg = g; }
            gmask |= 1u << bg;
        }

        float mv[8];
        #pragma unroll
        for (int j = 0; j < 8; j++)
            mv[j] = ((gmask >> j) & 1) ? s_sc[t][lane + 32 * j] : -INFINITY;

        int sel[8];
        #pragma unroll
        for (int r = 0; r < 8; r++) {
            float bv = -INFINITY; int be = 1 << 30;
            #pragma unroll
            for (int j = 0; j < 8; j++) {
                int e = lane + 32 * j;
                if (mv[j] > bv || (mv[j] == bv && e < be)) { bv = mv[j]; be = e; }
            }
            for (int off = 16; off; off >>= 1) {
                float ov = __shfl_xor_sync(~0u, bv, off);
                int   oe = __shfl_xor_sync(~0u, be, off);
                if (ov > bv || (ov == bv && oe < be)) { bv = ov; be = oe; }
            }
            sel[r] = be;
            if ((be & 31) == lane) mv[be >> 5] = -INFINITY;
        }

        float myv = (lane < 8) ? s_scores[t][sel[lane]] : 0.f;
        float sum = myv;
        for (int off = 16; off; off >>= 1)
            sum += __shfl_xor_sync(~0u, sum, off);
        if (lane < 8) {
            float wt = myv / (sum + 1e-20f) * 2.5f;
            int e = sel[lane];
            int pos = atomicAdd(&d_cnt[e], 1);
            d_tokbuf[e * T + pos] = tglob;
            d_wbuf[e * T + pos]  = wt;
        }
    }
}

// ============================================================
// 2) scan: segment list (cap 8). segs [0,32) = shared expert.
// ============================================================
__global__ void k_scan()
{
    __shared__ int s2[E];
    int e = threadIdx.x;
    int n = d_cnt[e];

    int nseg = (n + SEG_CAP - 1) / SEG_CAP;
    s2[e] = nseg; __syncthreads();
    for (int d = 1; d < E; d <<= 1) {
        int v = (e >= d) ? s2[e - d] : 0;
        __syncthreads();
        s2[e] += v;
        __syncthreads();
    }
    int segbase = 32 + (s2[e] - nseg);
    if (e == E - 1) d_nseg = 32 + s2[E - 1];

    for (int si = 0; si < nseg; si++) {
        int sidx = segbase + si;
        int st   = si * SEG_CAP;
        int cnt  = min(SEG_CAP, n - st);
        d_seg_e[sidx]  = e;
        d_seg_nt[sidx] = cnt;
        for (int j = 0; j < SEG_CAP; j++) {
            int jj = min(j, cnt - 1);
            d_seg_tok[sidx * SEG_CAP + j] = d_tokbuf[e * T + st + jj];
            d_seg_wt[sidx * SEG_CAP + j]  = (j < cnt) ? d_wbuf[e * T + st + j] : 0.f;
        }
    }

    // shared-expert segments [0,32): 8 consecutive tokens each, wt 1
    if (e < 32) {
        d_seg_e[e]  = E;
        d_seg_nt[e] = SEG_CAP;
        for (int j = 0; j < SEG_CAP; j++) {
            d_seg_tok[e * SEG_CAP + j] = e * SEG_CAP + j;
            d_seg_wt[e * SEG_CAP + j]  = 1.0f;
        }
    }
}

// ---- inner step: 1 weight float2 (2 cols) x 4 token-pairs ----
#define UP_STEP2(W, XR)                                         \
    {                                                           \
        ulonglong2 xa = *(const ulonglong2*)(XR);               \
        ulonglong2 xb = *(const ulonglong2*)((XR) + 2);         \
        u64 wd0 = dup2f((W).x), wd1 = dup2f((W).y);             \
        acc[0] = fma2(xa.x, wd0, acc[0]);                       \
        acc[1] = fma2(xa.y, wd0, acc[1]);                       \
        acc[2] = fma2(xb.x, wd0, acc[2]);                       \
        acc[3] = fma2(xb.y, wd0, acc[3]);                       \
        acc[4] = fma2(xa.x, wd1, acc[4]);                       \
        acc[5] = fma2(xa.y, wd1, acc[5]);                       \
        acc[6] = fma2(xb.x, wd1, acc[6]);                       \
        acc[7] = fma2(xb.y, wd1, acc[7]);                       \
    }

// ============================================================
// 3) up/gate. grid (2, nseg). thread = (cp:64 col-pairs, m:
//    gate/up, s: k-half). 8-deep LDG batch for MLP.
// ============================================================
__global__ void __launch_bounds__(256, 3) k_up(
    const float* __restrict__ x,
    const float* __restrict__ w_gate, const float* __restrict__ w_up,
    const float* __restrict__ sw_gate, const float* __restrict__ sw_up)
{
    extern __shared__ u64 dsm[];        // 4096 u64 = 32 KB
    __shared__ int s_tok[SEG_CAP];
    int seg = blockIdx.y;
    if (seg >= d_nseg) return;
    int e  = d_seg_e[seg];
    int ic = blockIdx.x;
    int tid = threadIdx.x;
    int cp = tid & 63;
    int m  = (tid >> 6) & 1;
    int s  = tid >> 7;

    if (tid < SEG_CAP) s_tok[tid] = d_seg_tok[seg * SEG_CAP + tid];
    __syncthreads();

    // stage x token-pairs: coalesced per token row
    for (int idx = tid; idx < 4096; idx += 256) {
        int tp = idx >> 10;
        int k  = idx & 1023;
        float a = x[(size_t)s_tok[2 * tp]     * H + k];
        float b = x[(size_t)s_tok[2 * tp + 1] * H + k];
        dsm[(size_t)k * 4 + tp] = pk2(a, b);
    }
    __syncthreads();

    const float* wf;
    if (e < E) wf = m ? (w_up + (size_t)e * H * I_DIM) : (w_gate + (size_t)e * H * I_DIM);
    else       wf = m ? sw_up : sw_gate;
    // float2 view: row stride 128; block covers cols [128*ic, 128*ic+128)
    const float2* wp = (const float2*)wf + (size_t)(s * 512) * 128 + ic * 64 + cp;

    u64 acc[8];
    #pragma unroll
    for (int j = 0; j < 8; j++) acc[j] = 0ull;

    const u64* xb0 = dsm + (size_t)(s * 512) * 4;
    #pragma unroll 1
    for (int k0 = 0; k0 < 512; k0 += 8) {
        float2 w0 = wp[(size_t)(k0 + 0) * 128];
        float2 w1 = wp[(size_t)(k0 + 1) * 128];
        float2 w2 = wp[(size_t)(k0 + 2) * 128];
        float2 w3 = wp[(size_t)(k0 + 3) * 128];
        float2 w4 = wp[(size_t)(k0 + 4) * 128];
        float2 w5 = wp[(size_t)(k0 + 5) * 128];
        float2 w6 = wp[(size_t)(k0 + 6) * 128];
        float2 w7 = wp[(size_t)(k0 + 7) * 128];
        UP_STEP2(w0, xb0 + (size_t)(k0 + 0) * 4);
        UP_STEP2(w1, xb0 + (size_t)(k0 + 1) * 4);
        UP_STEP2(w2, xb0 + (size_t)(k0 + 2) * 4);
        UP_STEP2(w3, xb0 + (size_t)(k0 + 3) * 4);
        UP_STEP2(w4, xb0 + (size_t)(k0 + 4) * 4);
        UP_STEP2(w5, xb0 + (size_t)(k0 + 5) * 4);
        UP_STEP2(w6, xb0 + (size_t)(k0 + 6) * 4);
        UP_STEP2(w7, xb0 + (size_t)(k0 + 7) * 4);
    }

    // cross-s reduction + silu combine
    __syncthreads();
    if (s == 0) {
        #pragma unroll
        for (int j = 0; j < 8; j++)
            dsm[(size_t)(m * 64 + cp) * 8 + j] = acc[j];
    }
    __syncthreads();
    if (s == 1) {
        #pragma unroll
        for (int j = 0; j < 8; j++)
            acc[j] = add2(acc[j], dsm[(size_t)(m * 64 + cp) * 8 + j]);
        if (m == 0) {
            #pragma unroll
            for (int j = 0; j < 8; j++)
                dsm[(size_t)(128 + cp) * 8 + j] = acc[j];
        }
    }
    __syncthreads();
    if (s == 1 && m == 1) {
        u64* psout = d_ps + (size_t)seg * 1024;
        #pragma unroll
        for (int c = 0; c < 2; c++) {
            #pragma unroll
            for (int tp = 0; tp < 4; tp++) {
                float2 g = unpk(dsm[(size_t)(128 + cp) * 8 + c * 4 + tp]);
                float2 u = unpk(acc[c * 4 + tp]);
                float r0 = g.x / (1.f + expf(-g.x)) * u.x;
                float r1 = g.y / (1.f + expf(-g.y)) * u.y;
                psout[(size_t)(ic * 128 + 2 * cp + c) * 4 + tp] = pk2(r0, r1);
            }
        }
    }
}

// ============================================================
// 4) down. grid (2, nseg). thread = 2 adjacent h-cols, full i.
//    8-deep LDG batch. ps staged as direct u64 copy (8 KB).
// ============================================================
__global__ void __launch_bounds__(256, 3) k_down(
    const float* __restrict__ w_down, const float* __restrict__ sw_down,
    float* __restrict__ y)
{
    extern __shared__ u64 pd[];         // 1024 u64 = 8 KB
    __shared__ int   s_tok[SEG_CAP];
    __shared__ float s_wt[SEG_CAP];
    int seg = blockIdx.y;
    if (seg >= d_nseg) return;
    int e  = d_seg_e[seg];
    int hc = blockIdx.x;
    int tid = threadIdx.x;

    if (tid < SEG_CAP) {
        s_tok[tid] = d_seg_tok[seg * SEG_CAP + tid];
        s_wt[tid]  = d_seg_wt[seg * SEG_CAP + tid];
    }
    // stage ps: straight copy
    const u64* psin = d_ps + (size_t)seg * 1024;
    {
        const ulonglong2* src = (const ulonglong2*)psin;
        ulonglong2* dst = (ulonglong2*)pd;
        dst[tid]       = src[tid];
        dst[tid + 256] = src[tid + 256];
    }
    __syncthreads();

    const float2* wp = (const float2*)((e < E) ? (w_down + (size_t)e * I_DIM * H) : sw_down)
                       + hc * 256 + tid;

    u64 acc[8];
    #pragma unroll
    for (int j = 0; j < 8; j++) acc[j] = 0ull;

    #pragma unroll 1
    for (int i0 = 0; i0 < 256; i0 += 8) {
        float2 w0 = wp[(size_t)(i0 + 0) * 512];
        float2 w1 = wp[(size_t)(i0 + 1) * 512];
        float2 w2 = wp[(size_t)(i0 + 2) * 512];
        float2 w3 = wp[(size_t)(i0 + 3) * 512];
        float2 w4 = wp[(size_t)(i0 + 4) * 512];
        float2 w5 = wp[(size_t)(i0 + 5) * 512];
        float2 w6 = wp[(size_t)(i0 + 6) * 512];
        float2 w7 = wp[(size_t)(i0 + 7) * 512];
        #pragma unroll
        for (int r = 0; r < 8; r++) {
            float2 w = (r == 0) ? w0 : (r == 1) ? w1 : (r == 2) ? w2 : (r == 3) ? w3
                     : (r == 4) ? w4 : (r == 5) ? w5 : (r == 6) ? w6 : w7;
            const u64* xr = pd + (size_t)(i0 + r) * 4;
            ulonglong2 xa = *(const ulonglong2*)xr;
            ulonglong2 xb = *(const ulonglong2*)(xr + 2);
            u64 wd0 = dup2f(w.x), wd1 = dup2f(w.y);
            acc[0] = fma2(xa.x, wd0, acc[0]);
            acc[1] = fma2(xa.y, wd0, acc[1]);
            acc[2] = fma2(xb.x, wd0, acc[2]);
            acc[3] = fma2(xb.y, wd0, acc[3]);
            acc[4] = fma2(xa.x, wd1, acc[4]);
            acc[5] = fma2(xa.y, wd1, acc[5]);
            acc[6] = fma2(xb.x, wd1, acc[6]);
            acc[7] = fma2(xb.y, wd1, acc[7]);
        }
    }

    int col0 = hc * 512 + 2 * tid;
    #pragma unroll
    for (int c = 0; c < 2; c++) {
        #pragma unroll
        for (int tp = 0; tp < 4; tp++) {
            float2 v = unpk(acc[c * 4 + tp]);
            int t0 = 2 * tp, t1 = 2 * tp + 1;
            atomicAdd(&y[(size_t)s_tok[t0] * H + col0 + c], s_wt[t0] * v.x);
            atomicAdd(&y[(size_t)s_tok[t1] * H + col0 + c], s_wt[t1] * v.y);
        }
    }
}

// ============================================================
extern "C" void kernel_launch(void* const* d_in, const int* in_sizes, int n_in,
                              void* d_out, int out_size)
{
    const float* x   = (const float*)d_in[0];
    const float* gw  = (const float*)d_in[1];
    const float* eb  = (const float*)d_in[2];
    const float* wg  = (const float*)d_in[3];
    const float* wu  = (const float*)d_in[4];
    const float* wd  = (const float*)d_in[5];
    const float* swg = (const float*)d_in[6];
    const float* swu = (const float*)d_in[7];
    const float* swd = (const float*)d_in[8];
    float* y = (float*)d_out;

    static int attr_done = 0;
    if (!attr_done) {
        cudaFuncSetAttribute(k_up,   cudaFuncAttributeMaxDynamicSharedMemorySize, 32768);
        cudaFuncSetAttribute(k_down, cudaFuncAttributeMaxDynamicSharedMemorySize, 8192);
        attr_done = 1;
    }

    k_init<<<256, 256>>>((float4*)y);
    k_route<<<64, 256>>>(x, gw, eb);
    k_scan<<<1, 256>>>();
    k_up<<<dim3(2, NSEG_MAX), 256, 32768>>>(x, wg, wu, swg, swu);
    k_down<<<dim3(2, NSEG_MAX), 256, 8192>>>(wd, swd, y);
}

// round 12
// speedup vs baseline: 1.4468x; 1.4468x over previous
#include <cuda_runtime.h>
#include <math.h>

#define T 256
#define H 1024
#define E 256
#define I_DIM 256
#define SEG_CAP 8
#define NSEG_MAX 544

typedef unsigned long long u64;

// ---- static scratch ----
__device__ int   d_cnt[E];
__device__ int   d_tokbuf[E * T];
__device__ float d_wbuf[E * T];
__device__ int   d_nseg;
__device__ int   d_seg_e[NSEG_MAX];
__device__ int   d_seg_nt[NSEG_MAX];
__device__ int   d_seg_tok[NSEG_MAX * SEG_CAP];
__device__ float d_seg_wt[NSEG_MAX * SEG_CAP];
// ps: per-seg [256 i][4 token-pair u64]  (f32x2 = {tok2p, tok2p+1})
__device__ __align__(16) u64 d_ps[NSEG_MAX * I_DIM * 4];

// ---- f32x2 helpers ----
__device__ __forceinline__ u64 dup2f(float v) {
    u64 r; asm("mov.b64 %0,{%1,%1};" : "=l"(r) : "f"(v)); return r;
}
__device__ __forceinline__ u64 pk2(float a, float b) {
    u64 r; asm("mov.b64 %0,{%1,%2};" : "=l"(r) : "f"(a), "f"(b)); return r;
}
__device__ __forceinline__ u64 fma2(u64 a, u64 b, u64 c) {
    u64 d; asm("fma.rn.f32x2 %0,%1,%2,%3;" : "=l"(d) : "l"(a), "l"(b), "l"(c)); return d;
}
__device__ __forceinline__ u64 add2(u64 a, u64 b) {
    u64 d; asm("add.rn.f32x2 %0,%1,%2;" : "=l"(d) : "l"(a), "l"(b)); return d;
}
__device__ __forceinline__ float2 unpk(u64 a) {
    float2 f; asm("mov.b64 {%0,%1},%2;" : "=f"(f.x), "=f"(f.y) : "l"(a)); return f;
}

// ============================================================
// 0) init: zero output + per-expert counters
// ============================================================
__global__ void k_init(float4* y)
{
    y[blockIdx.x * 256 + threadIdx.x] = make_float4(0.f, 0.f, 0.f, 0.f);
    if (blockIdx.x == 0) d_cnt[threadIdx.x] = 0;
}

// ============================================================
// 1) gate logits + noaux_tc routing. 4 tokens per block.
// ============================================================
__global__ void k_route(const float* __restrict__ x,
                        const float* __restrict__ gw,
                        const float* __restrict__ ebias)
{
    __shared__ float xs[4][H];
    __shared__ float s_scores[4][E];
    __shared__ float s_sc[4][E];

    int tid  = threadIdx.x;
    int lane = tid & 31;
    int wid  = tid >> 5;
    int t0   = blockIdx.x * 4;

    for (int t = 0; t < 4; t++)
        for (int k = tid; k < H; k += 256)
            xs[t][k] = x[(t0 + t) * H + k];
    __syncthreads();

    for (int eo = 0; eo < 32; eo++) {
        int e = wid * 32 + eo;
        const float* wr = gw + e * H;
        float a0 = 0.f, a1 = 0.f, a2 = 0.f, a3 = 0.f;
        #pragma unroll 4
        for (int k = 0; k < 32; k++) {
            float wv = wr[k * 32 + lane];
            a0 += wv * xs[0][k * 32 + lane];
            a1 += wv * xs[1][k * 32 + lane];
            a2 += wv * xs[2][k * 32 + lane];
            a3 += wv * xs[3][k * 32 + lane];
        }
        for (int off = 16; off; off >>= 1) {
            a0 += __shfl_xor_sync(~0u, a0, off);
            a1 += __shfl_xor_sync(~0u, a1, off);
            a2 += __shfl_xor_sync(~0u, a2, off);
            a3 += __shfl_xor_sync(~0u, a3, off);
        }
        if (lane == 0) {
            float b = ebias[e];
            float s;
            s = 1.f / (1.f + expf(-a0)); s_scores[0][e] = s; s_sc[0][e] = s + b;
            s = 1.f / (1.f + expf(-a1)); s_scores[1][e] = s; s_sc[1][e] = s + b;
            s = 1.f / (1.f + expf(-a2)); s_scores[2][e] = s; s_sc[2][e] = s + b;
            s = 1.f / (1.f + expf(-a3)); s_scores[3][e] = s; s_sc[3][e] = s + b;
        }
    }
    __syncthreads();

    if (wid < 4) {
        int t     = wid;
        int tglob = t0 + t;

        float gs[8];
        #pragma unroll
        for (int g = 0; g < 8; g++) {
            float v  = s_sc[t][g * 32 + lane];
            float m1 = v; int i1 = lane;
            for (int off = 16; off; off >>= 1) {
                float ov = __shfl_xor_sync(~0u, m1, off);
                int   oi = __shfl_xor_sync(~0u, i1, off);
                if (ov > m1 || (ov == m1 && oi < i1)) { m1 = ov; i1 = oi; }
            }
            float v2 = (lane == i1) ? -INFINITY : v;
            for (int off = 16; off; off >>= 1)
                v2 = fmaxf(v2, __shfl_xor_sync(~0u, v2, off));
            gs[g] = m1 + v2;
        }

        unsigned gmask = 0;
        #pragma unroll
        for (int r = 0; r < 4; r++) {
            float bv = -INFINITY; int bg = 0;
            #pragma unroll
            for (int g = 0; g < 8; g++)
                if (!((gmask >> g) & 1) && gs[g] > bv) { bv = gs[g]; bg = g; }
            gmask |= 1u << bg;
        }

        float mv[8];
        #pragma unroll
        for (int j = 0; j < 8; j++)
            mv[j] = ((gmask >> j) & 1) ? s_sc[t][lane + 32 * j] : -INFINITY;

        int sel[8];
        #pragma unroll
        for (int r = 0; r < 8; r++) {
            float bv = -INFINITY; int be = 1 << 30;
            #pragma unroll
            for (int j = 0; j < 8; j++) {
                int e = lane + 32 * j;
                if (mv[j] > bv || (mv[j] == bv && e < be)) { bv = mv[j]; be = e; }
            }
            for (int off = 16; off; off >>= 1) {
                float ov = __shfl_xor_sync(~0u, bv, off);
                int   oe = __shfl_xor_sync(~0u, be, off);
                if (ov > bv || (ov == bv && oe < be)) { bv = ov; be = oe; }
            }
            sel[r] = be;
            if ((be & 31) == lane) mv[be >> 5] = -INFINITY;
        }

        float myv = (lane < 8) ? s_scores[t][sel[lane]] : 0.f;
        float sum = myv;
        for (int off = 16; off; off >>= 1)
            sum += __shfl_xor_sync(~0u, sum, off);
        if (lane < 8) {
            float wt = myv / (sum + 1e-20f) * 2.5f;
            int e = sel[lane];
            int pos = atomicAdd(&d_cnt[e], 1);
            d_tokbuf[e * T + pos] = tglob;
            d_wbuf[e * T + pos]  = wt;
        }
    }
}

// ============================================================
// 2) scan: segment list (cap 8). segs [0,32) = shared expert.
// ============================================================
__global__ void k_scan()
{
    __shared__ int s2[E];
    int e = threadIdx.x;
    int n = d_cnt[e];

    int nseg = (n + SEG_CAP - 1) / SEG_CAP;
    s2[e] = nseg; __syncthreads();
    for (int d = 1; d < E; d <<= 1) {
        int v = (e >= d) ? s2[e - d] : 0;
        __syncthreads();
        s2[e] += v;
        __syncthreads();
    }
    int segbase = 32 + (s2[e] - nseg);
    if (e == E - 1) d_nseg = 32 + s2[E - 1];

    for (int si = 0; si < nseg; si++) {
        int sidx = segbase + si;
        int st   = si * SEG_CAP;
        int cnt  = min(SEG_CAP, n - st);
        d_seg_e[sidx]  = e;
        d_seg_nt[sidx] = cnt;
        for (int j = 0; j < SEG_CAP; j++) {
            int jj = min(j, cnt - 1);
            d_seg_tok[sidx * SEG_CAP + j] = d_tokbuf[e * T + st + jj];
            d_seg_wt[sidx * SEG_CAP + j]  = (j < cnt) ? d_wbuf[e * T + st + j] : 0.f;
        }
    }

    // shared-expert segments [0,32): 8 consecutive tokens each, wt 1
    if (e < 32) {
        d_seg_e[e]  = E;
        d_seg_nt[e] = SEG_CAP;
        for (int j = 0; j < SEG_CAP; j++) {
            d_seg_tok[e * SEG_CAP + j] = e * SEG_CAP + j;
            d_seg_wt[e * SEG_CAP + j]  = 1.0f;
        }
    }
}

// ---- inner step: 1 weight float4 (4 cols) x 4 token-pairs ----
// acc[c*4+tp], c in [0,4), tp in [0,4)
#define STEP4(W, XR)                                            \
    {                                                           \
        ulonglong2 xa = *(const ulonglong2*)(XR);               \
        ulonglong2 xb = *(const ulonglong2*)((XR) + 2);         \
        u64 wd0 = dup2f((W).x), wd1 = dup2f((W).y);             \
        u64 wd2 = dup2f((W).z), wd3 = dup2f((W).w);             \
        acc[0]  = fma2(xa.x, wd0, acc[0]);                      \
        acc[1]  = fma2(xa.y, wd0, acc[1]);                      \
        acc[2]  = fma2(xb.x, wd0, acc[2]);                      \
        acc[3]  = fma2(xb.y, wd0, acc[3]);                      \
        acc[4]  = fma2(xa.x, wd1, acc[4]);                      \
        acc[5]  = fma2(xa.y, wd1, acc[5]);                      \
        acc[6]  = fma2(xb.x, wd1, acc[6]);                      \
        acc[7]  = fma2(xb.y, wd1, acc[7]);                      \
        acc[8]  = fma2(xa.x, wd2, acc[8]);                      \
        acc[9]  = fma2(xa.y, wd2, acc[9]);                      \
        acc[10] = fma2(xb.x, wd2, acc[10]);                     \
        acc[11] = fma2(xb.y, wd2, acc[11]);                     \
        acc[12] = fma2(xa.x, wd3, acc[12]);                     \
        acc[13] = fma2(xa.y, wd3, acc[13]);                     \
        acc[14] = fma2(xb.x, wd3, acc[14]);                     \
        acc[15] = fma2(xb.y, wd3, acc[15]);                     \
    }

// ============================================================
// 3) up/gate. grid (2, nseg). thread = (cp:32 groups of 4 cols,
//    m: gate/up, s: k-quarter). 32cp*4 = 128 cols = ic half.
//    LDG.128 weights, 4-deep batch (2 KB/warp in flight).
//    acc = 16 u64. Cross-s reduction + silu in smem epilogue.
// ============================================================
__global__ void __launch_bounds__(256, 3) k_up(
    const float* __restrict__ x,
    const float* __restrict__ w_gate, const float* __restrict__ w_up,
    const float* __restrict__ sw_gate, const float* __restrict__ sw_up)
{
    extern __shared__ u64 dsm[];        // 4096 u64 = 32 KB (x stage / red)
    __shared__ int s_tok[SEG_CAP];
    int seg = blockIdx.y;
    if (seg >= d_nseg) return;
    int e  = d_seg_e[seg];
    int ic = blockIdx.x;
    int tid = threadIdx.x;
    int cp = tid & 31;          // 4-col group
    int m  = (tid >> 5) & 1;    // gate/up
    int s  = tid >> 6;          // k-quarter 0..3

    if (tid < SEG_CAP) s_tok[tid] = d_seg_tok[seg * SEG_CAP + tid];
    __syncthreads();

    // stage x token-pairs: dsm[k*4 + tp] = {x_t2p[k], x_t2p+1[k]}
    for (int idx = tid; idx < 4096; idx += 256) {
        int tp = idx >> 10;
        int k  = idx & 1023;
        float a = x[(size_t)s_tok[2 * tp]     * H + k];
        float b = x[(size_t)s_tok[2 * tp + 1] * H + k];
        dsm[(size_t)k * 4 + tp] = pk2(a, b);
    }
    __syncthreads();

    const float* wf;
    if (e < E) wf = m ? (w_up + (size_t)e * H * I_DIM) : (w_gate + (size_t)e * H * I_DIM);
    else       wf = m ? sw_up : sw_gate;
    // float4 view: row stride 64; this thread's col group = ic*32 + cp
    const float4* wp = (const float4*)wf + (size_t)(s * 256) * 64 + ic * 32 + cp;

    u64 acc[16];
    #pragma unroll
    for (int j = 0; j < 16; j++) acc[j] = 0ull;

    const u64* xb0 = dsm + (size_t)(s * 256) * 4;
    #pragma unroll 2
    for (int k0 = 0; k0 < 256; k0 += 4) {
        float4 w0 = wp[(size_t)(k0 + 0) * 64];
        float4 w1 = wp[(size_t)(k0 + 1) * 64];
        float4 w2 = wp[(size_t)(k0 + 2) * 64];
        float4 w3 = wp[(size_t)(k0 + 3) * 64];
        STEP4(w0, xb0 + (size_t)(k0 + 0) * 4);
        STEP4(w1, xb0 + (size_t)(k0 + 1) * 4);
        STEP4(w2, xb0 + (size_t)(k0 + 2) * 4);
        STEP4(w3, xb0 + (size_t)(k0 + 3) * 4);
    }

    // epilogue: publish partials red[((m*32+cp)*4 + s)*16 + j]
    __syncthreads();
    #pragma unroll
    for (int j = 0; j < 16; j++)
        dsm[(((size_t)(m * 32 + cp)) * 4 + s) * 16 + j] = acc[j];
    __syncthreads();

    // combine: 512 results (128 cols x 4 tp), 2 per thread
    u64* psout = d_ps + (size_t)seg * 1024;
    #pragma unroll
    for (int q = 0; q < 2; q++) {
        int r   = 2 * tid + q;
        int col = r >> 2;           // 0..127
        int tp  = r & 3;
        int cpg = col >> 2;
        int c   = col & 3;
        int j   = c * 4 + tp;
        u64 g = add2(add2(dsm[(((size_t)(0 * 32 + cpg)) * 4 + 0) * 16 + j],
                          dsm[(((size_t)(0 * 32 + cpg)) * 4 + 1) * 16 + j]),
                     add2(dsm[(((size_t)(0 * 32 + cpg)) * 4 + 2) * 16 + j],
                          dsm[(((size_t)(0 * 32 + cpg)) * 4 + 3) * 16 + j]));
        u64 u = add2(add2(dsm[(((size_t)(1 * 32 + cpg)) * 4 + 0) * 16 + j],
                          dsm[(((size_t)(1 * 32 + cpg)) * 4 + 1) * 16 + j]),
                     add2(dsm[(((size_t)(1 * 32 + cpg)) * 4 + 2) * 16 + j],
                          dsm[(((size_t)(1 * 32 + cpg)) * 4 + 3) * 16 + j]));
        float2 gv = unpk(g), uv = unpk(u);
        float r0 = gv.x / (1.f + expf(-gv.x)) * uv.x;
        float r1 = gv.y / (1.f + expf(-gv.y)) * uv.y;
        psout[(size_t)(ic * 128 + col) * 4 + tp] = pk2(r0, r1);
    }
}

// ============================================================
// 4) down. grid (2, nseg). thread = (cp:128 groups of 4 cols,
//    g2: i-half). 128cp*4 = 512 cols = hc half. LDG.128, 4-deep.
//    acc = 16 u64. Cross-g2 reduction in smem, then atomics.
// ============================================================
__global__ void __launch_bounds__(256, 3) k_down(
    const float* __restrict__ w_down, const float* __restrict__ sw_down,
    float* __restrict__ y)
{
    extern __shared__ u64 dsm[];        // 4096 u64 = 32 KB (ps in [0,1024) / red)
    __shared__ int   s_tok[SEG_CAP];
    __shared__ float s_wt[SEG_CAP];
    int seg = blockIdx.y;
    if (seg >= d_nseg) return;
    int e  = d_seg_e[seg];
    int hc = blockIdx.x;
    int tid = threadIdx.x;
    int cp = tid & 127;         // 4-col group within the 512-col half
    int g2 = tid >> 7;          // i-half

    if (tid < SEG_CAP) {
        s_tok[tid] = d_seg_tok[seg * SEG_CAP + tid];
        s_wt[tid]  = d_seg_wt[seg * SEG_CAP + tid];
    }
    // stage ps: straight copy into dsm[0,1024)
    const u64* psin = d_ps + (size_t)seg * 1024;
    {
        const ulonglong2* src = (const ulonglong2*)psin;
        ulonglong2* dst = (ulonglong2*)dsm;
        dst[tid]       = src[tid];
        dst[tid + 256] = src[tid + 256];
    }
    __syncthreads();

    // float4 view: row stride 256; this thread's col group = hc*128 + cp
    const float4* wp = (const float4*)((e < E) ? (w_down + (size_t)e * I_DIM * H) : sw_down)
                       + (size_t)(g2 * 128) * 256 + hc * 128 + cp;

    u64 acc[16];
    #pragma unroll
    for (int j = 0; j < 16; j++) acc[j] = 0ull;

    const u64* pb0 = dsm + (size_t)(g2 * 128) * 4;
    #pragma unroll 2
    for (int i0 = 0; i0 < 128; i0 += 4) {
        float4 w0 = wp[(size_t)(i0 + 0) * 256];
        float4 w1 = wp[(size_t)(i0 + 1) * 256];
        float4 w2 = wp[(size_t)(i0 + 2) * 256];
        float4 w3 = wp[(size_t)(i0 + 3) * 256];
        STEP4(w0, pb0 + (size_t)(i0 + 0) * 4);
        STEP4(w1, pb0 + (size_t)(i0 + 1) * 4);
        STEP4(w2, pb0 + (size_t)(i0 + 2) * 4);
        STEP4(w3, pb0 + (size_t)(i0 + 3) * 4);
    }

    // epilogue: publish partials red[(cp*2 + g2)*16 + j]  (overwrites ps)
    __syncthreads();
    #pragma unroll
    for (int j = 0; j < 16; j++)
        dsm[(((size_t)cp) * 2 + g2) * 16 + j] = acc[j];
    __syncthreads();

    // combine: 2048 results (512 cols x 4 tp), 8 per thread -> atomics
    int colbase = hc * 512;
    #pragma unroll
    for (int q = 0; q < 8; q++) {
        int r   = tid * 8 + q;
        int col = r >> 2;           // 0..511
        int tp  = r & 3;
        int cpg = col >> 2;
        int c   = col & 3;
        int j   = c * 4 + tp;
        u64 v = add2(dsm[(((size_t)cpg) * 2 + 0) * 16 + j],
                     dsm[(((size_t)cpg) * 2 + 1) * 16 + j]);
        float2 vv = unpk(v);
        int t0 = 2 * tp, t1 = 2 * tp + 1;
        atomicAdd(&y[(size_t)s_tok[t0] * H + colbase + col], s_wt[t0] * vv.x);
        atomicAdd(&y[(size_t)s_tok[t1] * H + colbase + col], s_wt[t1] * vv.y);
    }
}

// ============================================================
extern "C" void kernel_launch(void* const* d_in, const int* in_sizes, int n_in,
                              void* d_out, int out_size)
{
    const float* x   = (const float*)d_in[0];
    const float* gw  = (const float*)d_in[1];
    const float* eb  = (const float*)d_in[2];
    const float* wg  = (const float*)d_in[3];
    const float* wu  = (const float*)d_in[4];
    const float* wd  = (const float*)d_in[5];
    const float* swg = (const float*)d_in[6];
    const float* swu = (const float*)d_in[7];
    const float* swd = (const float*)d_in[8];
    float* y = (float*)d_out;

    static int attr_done = 0;
    if (!attr_done) {
        cudaFuncSetAttribute(k_up,   cudaFuncAttributeMaxDynamicSharedMemorySize, 32768);
        cudaFuncSetAttribute(k_down, cudaFuncAttributeMaxDynamicSharedMemorySize, 32768);
        attr_done = 1;
    }

    k_init<<<256, 256>>>((float4*)y);
    k_route<<<64, 256>>>(x, gw, eb);
    k_scan<<<1, 256>>>();
    k_up<<<dim3(2, NSEG_MAX), 256, 32768>>>(x, wg, wu, swg, swu);
    k_down<<<dim3(2, NSEG_MAX), 256, 32768>>>(wd, swd, y);
}

// round 13
// speedup vs baseline: 1.5604x; 1.0785x over previous
#include <cuda_runtime.h>
#include <math.h>

#define T 256
#define H 1024
#define E 256
#define I_DIM 256
#define SEG_CAP 8
#define NSEG_MAX 544

typedef unsigned long long u64;

// ---- static scratch ----
__device__ int   d_cnt[E];          // .bss zero at load; re-zeroed at end of k_scan
__device__ int   d_tokbuf[E * T];
__device__ float d_wbuf[E * T];
__device__ int   d_nseg;
__device__ int   d_seg_e[NSEG_MAX];
__device__ int   d_seg_nt[NSEG_MAX];
__device__ int   d_seg_tok[NSEG_MAX * SEG_CAP];
__device__ float d_seg_wt[NSEG_MAX * SEG_CAP];
// ps: per-seg [256 i][4 token-pair u64]  (f32x2 = {tok2p, tok2p+1})
__device__ __align__(16) u64 d_ps[NSEG_MAX * I_DIM * 4];

// ---- f32x2 helpers ----
__device__ __forceinline__ u64 dup2f(float v) {
    u64 r; asm("mov.b64 %0,{%1,%1};" : "=l"(r) : "f"(v)); return r;
}
__device__ __forceinline__ u64 pk2(float a, float b) {
    u64 r; asm("mov.b64 %0,{%1,%2};" : "=l"(r) : "f"(a), "f"(b)); return r;
}
__device__ __forceinline__ u64 fma2(u64 a, u64 b, u64 c) {
    u64 d; asm("fma.rn.f32x2 %0,%1,%2,%3;" : "=l"(d) : "l"(a), "l"(b), "l"(c)); return d;
}
__device__ __forceinline__ u64 add2(u64 a, u64 b) {
    u64 d; asm("add.rn.f32x2 %0,%1,%2;" : "=l"(d) : "l"(a), "l"(b)); return d;
}
__device__ __forceinline__ float2 unpk(u64 a) {
    float2 f; asm("mov.b64 {%0,%1},%2;" : "=f"(f.x), "=f"(f.y) : "l"(a)); return f;
}

// ============================================================
// 1) gate logits + noaux_tc routing. 4 tokens per block.
//    Also zeroes this block's share of y (y unread until k_down).
// ============================================================
__global__ void k_route(const float* __restrict__ x,
                        const float* __restrict__ gw,
                        const float* __restrict__ ebias,
                        float4* __restrict__ y4)
{
    __shared__ float xs[4][H];
    __shared__ float s_scores[4][E];
    __shared__ float s_sc[4][E];

    int tid  = threadIdx.x;
    int lane = tid & 31;
    int wid  = tid >> 5;
    int t0   = blockIdx.x * 4;

    // zero y share: 64 blocks x 1024 float4 = full T*H
    #pragma unroll
    for (int q = 0; q < 4; q++)
        y4[blockIdx.x * 1024 + q * 256 + tid] = make_float4(0.f, 0.f, 0.f, 0.f);

    for (int t = 0; t < 4; t++)
        for (int k = tid; k < H; k += 256)
            xs[t][k] = x[(t0 + t) * H + k];
    __syncthreads();

    for (int eo = 0; eo < 32; eo++) {
        int e = wid * 32 + eo;
        const float* wr = gw + e * H;
        float a0 = 0.f, a1 = 0.f, a2 = 0.f, a3 = 0.f;
        #pragma unroll 4
        for (int k = 0; k < 32; k++) {
            float wv = wr[k * 32 + lane];
            a0 += wv * xs[0][k * 32 + lane];
            a1 += wv * xs[1][k * 32 + lane];
            a2 += wv * xs[2][k * 32 + lane];
            a3 += wv * xs[3][k * 32 + lane];
        }
        for (int off = 16; off; off >>= 1) {
            a0 += __shfl_xor_sync(~0u, a0, off);
            a1 += __shfl_xor_sync(~0u, a1, off);
            a2 += __shfl_xor_sync(~0u, a2, off);
            a3 += __shfl_xor_sync(~0u, a3, off);
        }
        if (lane == 0) {
            float b = ebias[e];
            float s;
            s = 1.f / (1.f + expf(-a0)); s_scores[0][e] = s; s_sc[0][e] = s + b;
            s = 1.f / (1.f + expf(-a1)); s_scores[1][e] = s; s_sc[1][e] = s + b;
            s = 1.f / (1.f + expf(-a2)); s_scores[2][e] = s; s_sc[2][e] = s + b;
            s = 1.f / (1.f + expf(-a3)); s_scores[3][e] = s; s_sc[3][e] = s + b;
        }
    }
    __syncthreads();

    if (wid < 4) {
        int t     = wid;
        int tglob = t0 + t;

        float gs[8];
        #pragma unroll
        for (int g = 0; g < 8; g++) {
            float v  = s_sc[t][g * 32 + lane];
            float m1 = v; int i1 = lane;
            for (int off = 16; off; off >>= 1) {
                float ov = __shfl_xor_sync(~0u, m1, off);
                int   oi = __shfl_xor_sync(~0u, i1, off);
                if (ov > m1 || (ov == m1 && oi < i1)) { m1 = ov; i1 = oi; }
            }
            float v2 = (lane == i1) ? -INFINITY : v;
            for (int off = 16; off; off >>= 1)
                v2 = fmaxf(v2, __shfl_xor_sync(~0u, v2, off));
            gs[g] = m1 + v2;
        }

        unsigned gmask = 0;
        #pragma unroll
        for (int r = 0; r < 4; r++) {
            float bv = -INFINITY; int bg = 0;
            #pragma unroll
            for (int g = 0; g < 8; g++)
                if (!((gmask >> g) & 1) && gs[g] > bv) { bv = gs[g]; bg = g; }
            gmask |= 1u << bg;
        }

        float mv[8];
        #pragma unroll
        for (int j = 0; j < 8; j++)
            mv[j] = ((gmask >> j) & 1) ? s_sc[t][lane + 32 * j] : -INFINITY;

        int sel[8];
        #pragma unroll
        for (int r = 0; r < 8; r++) {
            float bv = -INFINITY; int be = 1 << 30;
            #pragma unroll
            for (int j = 0; j < 8; j++) {
                int e = lane + 32 * j;
                if (mv[j] > bv || (mv[j] == bv && e < be)) { bv = mv[j]; be = e; }
            }
            for (int off = 16; off; off >>= 1) {
                float ov = __shfl_xor_sync(~0u, bv, off);
                int   oe = __shfl_xor_sync(~0u, be, off);
                if (ov > bv || (ov == bv && oe < be)) { bv = ov; be = oe; }
            }
            sel[r] = be;
            if ((be & 31) == lane) mv[be >> 5] = -INFINITY;
        }

        float myv = (lane < 8) ? s_scores[t][sel[lane]] : 0.f;
        float sum = myv;
        for (int off = 16; off; off >>= 1)
            sum += __shfl_xor_sync(~0u, sum, off);
        if (lane < 8) {
            float wt = myv / (sum + 1e-20f) * 2.5f;
            int e = sel[lane];
            int pos = atomicAdd(&d_cnt[e], 1);
            d_tokbuf[e * T + pos] = tglob;
            d_wbuf[e * T + pos]  = wt;
        }
    }
}

// ============================================================
// 2) scan: segment list (cap 8). segs [0,32) = shared expert.
//    Zeroes d_cnt at the end (for the next graph replay).
// ============================================================
__global__ void k_scan()
{
    __shared__ int s2[E];
    int e = threadIdx.x;
    int n = d_cnt[e];

    int nseg = (n + SEG_CAP - 1) / SEG_CAP;
    s2[e] = nseg; __syncthreads();
    for (int d = 1; d < E; d <<= 1) {
        int v = (e >= d) ? s2[e - d] : 0;
        __syncthreads();
        s2[e] += v;
        __syncthreads();
    }
    int segbase = 32 + (s2[e] - nseg);
    if (e == E - 1) d_nseg = 32 + s2[E - 1];

    for (int si = 0; si < nseg; si++) {
        int sidx = segbase + si;
        int st   = si * SEG_CAP;
        int cnt  = min(SEG_CAP, n - st);
        d_seg_e[sidx]  = e;
        d_seg_nt[sidx] = cnt;
        for (int j = 0; j < SEG_CAP; j++) {
            int jj = min(j, cnt - 1);
            d_seg_tok[sidx * SEG_CAP + j] = d_tokbuf[e * T + st + jj];
            d_seg_wt[sidx * SEG_CAP + j]  = (j < cnt) ? d_wbuf[e * T + st + j] : 0.f;
        }
    }

    // shared-expert segments [0,32): 8 consecutive tokens each, wt 1
    if (e < 32) {
        d_seg_e[e]  = E;
        d_seg_nt[e] = SEG_CAP;
        for (int j = 0; j < SEG_CAP; j++) {
            d_seg_tok[e * SEG_CAP + j] = e * SEG_CAP + j;
            d_seg_wt[e * SEG_CAP + j]  = 1.0f;
        }
    }

    __syncthreads();
    d_cnt[e] = 0;   // reset for next replay (consumed above)
}

// ---- inner step: 1 weight float4 (4 cols) x 4 token-pairs ----
// acc[c*4+tp], c in [0,4), tp in [0,4)
#define STEP4(W, XR)                                            \
    {                                                           \
        ulonglong2 xa = *(const ulonglong2*)(XR);               \
        ulonglong2 xb = *(const ulonglong2*)((XR) + 2);         \
        u64 wd0 = dup2f((W).x), wd1 = dup2f((W).y);             \
        u64 wd2 = dup2f((W).z), wd3 = dup2f((W).w);             \
        acc[0]  = fma2(xa.x, wd0, acc[0]);                      \
        acc[1]  = fma2(xa.y, wd0, acc[1]);                      \
        acc[2]  = fma2(xb.x, wd0, acc[2]);                      \
        acc[3]  = fma2(xb.y, wd0, acc[3]);                      \
        acc[4]  = fma2(xa.x, wd1, acc[4]);                      \
        acc[5]  = fma2(xa.y, wd1, acc[5]);                      \
        acc[6]  = fma2(xb.x, wd1, acc[6]);                      \
        acc[7]  = fma2(xb.y, wd1, acc[7]);                      \
        acc[8]  = fma2(xa.x, wd2, acc[8]);                      \
        acc[9]  = fma2(xa.y, wd2, acc[9]);                      \
        acc[10] = fma2(xb.x, wd2, acc[10]);                     \
        acc[11] = fma2(xb.y, wd2, acc[11]);                     \
        acc[12] = fma2(xa.x, wd3, acc[12]);                     \
        acc[13] = fma2(xa.y, wd3, acc[13]);                     \
        acc[14] = fma2(xb.x, wd3, acc[14]);                     \
        acc[15] = fma2(xb.y, wd3, acc[15]);                     \
    }

// ============================================================
// 3) up/gate. 1 block per segment (all 256 cols). thread =
//    (cp:64 groups of 4 cols, m: gate/up, s: k-half of 512).
//    LDG.128 weights 4-deep. acc = 16 u64.
// ============================================================
__global__ void __launch_bounds__(256, 3) k_up(
    const float* __restrict__ x,
    const float* __restrict__ w_gate, const float* __restrict__ w_up,
    const float* __restrict__ sw_gate, const float* __restrict__ sw_up)
{
    extern __shared__ u64 dsm[];        // 4096 u64 = 32 KB (x stage / red)
    __shared__ int s_tok[SEG_CAP];
    int seg = blockIdx.x;
    if (seg >= d_nseg) return;
    int e   = d_seg_e[seg];
    int tid = threadIdx.x;
    int cp  = tid & 63;         // 4-col group (256 cols total)
    int m   = (tid >> 6) & 1;   // gate/up
    int s   = tid >> 7;         // k-half

    if (tid < SEG_CAP) s_tok[tid] = d_seg_tok[seg * SEG_CAP + tid];
    __syncthreads();

    // stage x token-pairs: dsm[k*4 + tp] = {x_t2p[k], x_t2p+1[k]}
    for (int idx = tid; idx < 4096; idx += 256) {
        int tp = idx >> 10;
        int k  = idx & 1023;
        float a = x[(size_t)s_tok[2 * tp]     * H + k];
        float b = x[(size_t)s_tok[2 * tp + 1] * H + k];
        dsm[(size_t)k * 4 + tp] = pk2(a, b);
    }
    __syncthreads();

    const float* wf;
    if (e < E) wf = m ? (w_up + (size_t)e * H * I_DIM) : (w_gate + (size_t)e * H * I_DIM);
    else       wf = m ? sw_up : sw_gate;
    const float4* wp = (const float4*)wf + (size_t)(s * 512) * 64 + cp;

    u64 acc[16];
    #pragma unroll
    for (int j = 0; j < 16; j++) acc[j] = 0ull;

    const u64* xb0 = dsm + (size_t)(s * 512) * 4;
    #pragma unroll 2
    for (int k0 = 0; k0 < 512; k0 += 4) {
        float4 w0 = wp[(size_t)(k0 + 0) * 64];
        float4 w1 = wp[(size_t)(k0 + 1) * 64];
        float4 w2 = wp[(size_t)(k0 + 2) * 64];
        float4 w3 = wp[(size_t)(k0 + 3) * 64];
        STEP4(w0, xb0 + (size_t)(k0 + 0) * 4);
        STEP4(w1, xb0 + (size_t)(k0 + 1) * 4);
        STEP4(w2, xb0 + (size_t)(k0 + 2) * 4);
        STEP4(w3, xb0 + (size_t)(k0 + 3) * 4);
    }

    // publish partials: red[((m*64+cp)*2 + s)*16 + j]  (4096 u64, reuses dsm)
    __syncthreads();
    #pragma unroll
    for (int j = 0; j < 16; j++)
        dsm[(((size_t)(m * 64 + cp)) * 2 + s) * 16 + j] = acc[j];
    __syncthreads();

    // combine: 1024 results (256 cols x 4 tp), 4 per thread
    u64* psout = d_ps + (size_t)seg * 1024;
    #pragma unroll
    for (int q = 0; q < 4; q++) {
        int r   = tid * 4 + q;
        int col = r >> 2;           // 0..255
        int tp  = r & 3;
        int cpg = col >> 2;
        int c   = col & 3;
        int j   = c * 4 + tp;
        u64 g = add2(dsm[(((size_t)(0 * 64 + cpg)) * 2 + 0) * 16 + j],
                     dsm[(((size_t)(0 * 64 + cpg)) * 2 + 1) * 16 + j]);
        u64 u = add2(dsm[(((size_t)(1 * 64 + cpg)) * 2 + 0) * 16 + j],
                     dsm[(((size_t)(1 * 64 + cpg)) * 2 + 1) * 16 + j]);
        float2 gv = unpk(g), uv = unpk(u);
        float r0 = gv.x / (1.f + expf(-gv.x)) * uv.x;
        float r1 = gv.y / (1.f + expf(-gv.y)) * uv.y;
        psout[(size_t)col * 4 + tp] = pk2(r0, r1);
    }
}

// ============================================================
// 4) down. 1 block per segment (all 1024 cols). thread =
//    cp:256 groups of 4 cols, full i=256. LDG.128 4-deep.
//    acc = 16 u64 -> direct atomics (no smem reduction).
// ============================================================
__global__ void __launch_bounds__(256, 3) k_down(
    const float* __restrict__ w_down, const float* __restrict__ sw_down,
    float* __restrict__ y)
{
    extern __shared__ u64 pd[];         // 1024 u64 = 8 KB
    __shared__ int   s_tok[SEG_CAP];
    __shared__ float s_wt[SEG_CAP];
    int seg = blockIdx.x;
    if (seg >= d_nseg) return;
    int e   = d_seg_e[seg];
    int tid = threadIdx.x;

    if (tid < SEG_CAP) {
        s_tok[tid] = d_seg_tok[seg * SEG_CAP + tid];
        s_wt[tid]  = d_seg_wt[seg * SEG_CAP + tid];
    }
    // stage ps: straight copy
    const u64* psin = d_ps + (size_t)seg * 1024;
    {
        const ulonglong2* src = (const ulonglong2*)psin;
        ulonglong2* dst = (ulonglong2*)pd;
        dst[tid]       = src[tid];
        dst[tid + 256] = src[tid + 256];
    }
    __syncthreads();

    // float4 view: row stride 256; this thread's col group = cp = tid
    const float4* wp = (const float4*)((e < E) ? (w_down + (size_t)e * I_DIM * H) : sw_down)
                       + tid;

    u64 acc[16];
    #pragma unroll
    for (int j = 0; j < 16; j++) acc[j] = 0ull;

    #pragma unroll 2
    for (int i0 = 0; i0 < 256; i0 += 4) {
        float4 w0 = wp[(size_t)(i0 + 0) * 256];
        float4 w1 = wp[(size_t)(i0 + 1) * 256];
        float4 w2 = wp[(size_t)(i0 + 2) * 256];
        float4 w3 = wp[(size_t)(i0 + 3) * 256];
        STEP4(w0, pd + (size_t)(i0 + 0) * 4);
        STEP4(w1, pd + (size_t)(i0 + 1) * 4);
        STEP4(w2, pd + (size_t)(i0 + 2) * 4);
        STEP4(w3, pd + (size_t)(i0 + 3) * 4);
    }

    // epilogue: direct atomics. cols 4*tid .. 4*tid+3
    int col0 = tid * 4;
    #pragma unroll
    for (int c = 0; c < 4; c++) {
        #pragma unroll
        for (int tp = 0; tp < 4; tp++) {
            float2 v = unpk(acc[c * 4 + tp]);
            int t0 = 2 * tp, t1 = 2 * tp + 1;
            atomicAdd(&y[(size_t)s_tok[t0] * H + col0 + c], s_wt[t0] * v.x);
            atomicAdd(&y[(size_t)s_tok[t1] * H + col0 + c], s_wt[t1] * v.y);
        }
    }
}

// ============================================================
extern "C" void kernel_launch(void* const* d_in, const int* in_sizes, int n_in,
                              void* d_out, int out_size)
{
    const float* x   = (const float*)d_in[0];
    const float* gw  = (const float*)d_in[1];
    const float* eb  = (const float*)d_in[2];
    const float* wg  = (const float*)d_in[3];
    const float* wu  = (const float*)d_in[4];
    const float* wd  = (const float*)d_in[5];
    const float* swg = (const float*)d_in[6];
    const float* swu = (const float*)d_in[7];
    const float* swd = (const float*)d_in[8];
    float* y = (float*)d_out;

    static int attr_done = 0;
    if (!attr_done) {
        cudaFuncSetAttribute(k_up,   cudaFuncAttributeMaxDynamicSharedMemorySize, 32768);
        cudaFuncSetAttribute(k_down, cudaFuncAttributeMaxDynamicSharedMemorySize, 8192);
        attr_done = 1;
    }

    k_route<<<64, 256>>>(x, gw, eb, (float4*)y);
    k_scan<<<1, 256>>>();
    k_up<<<NSEG_MAX, 256, 32768>>>(x, wg, wu, swg, swu);
    k_down<<<NSEG_MAX, 256, 8192>>>(wd, swd, y);
}